// round 4
// baseline (speedup 1.0000x reference)
#include <cuda_runtime.h>

#define FULLMASK 0xFFFFFFFFu

static constexpr int Bb = 2;
static constexpr int L  = 2048;
static constexpr int DM = 512;
static constexpr int H  = 8;
static constexpr int DK = 64;
static constexpr int U  = 38;     // int(5 * ln(2048)) = 38
static constexpr int BH = Bb * H; // 16

// ---------------- scratch (static device globals; no allocation) ----------------
__device__ float g_Q[(size_t)Bb * H * L * DK];     // 8 MB  head-major [bh][l][d]
__device__ float g_K[(size_t)Bb * H * L * DK];     // 8 MB
__device__ float g_V[(size_t)Bb * H * L * DK];     // 8 MB
__device__ float g_S[(size_t)Bb * H * L * L];      // 256 MB scores [bh][q][k]
__device__ float g_AO[(size_t)Bb * L * DM];        // 8 MB  attention out [b][l][dm]

// =====================================================================
// Shared SGEMM core: C(128x128) += A(128xK) * B(128xK)^T  (both K-major)
// 256 threads, 8x8 microtile, BK=16, register-staged pipeline.
// =====================================================================
__device__ __forceinline__ void gemm_core_128(
    const float* __restrict__ A, const float* __restrict__ Bm,
    int lda, int ldb, int Kc, float (&acc)[8][8])
{
    __shared__ float As[16][132];
    __shared__ float Bs[16][132];

    const int tid = threadIdx.x;
    const int tx  = tid & 15;
    const int ty  = tid >> 4;
    const int lr  = tid >> 2;          // 0..63  (tile row; +64 for second half)
    const int lc  = (tid & 3) << 2;    // 0,4,8,12 (k-column within BK)

    float4 a0, a1, b0, b1;
    // prologue: stage k-tile 0
    a0 = *(const float4*)(A + (size_t)lr * lda + lc);
    a1 = *(const float4*)(A + (size_t)(lr + 64) * lda + lc);
    b0 = *(const float4*)(Bm + (size_t)lr * ldb + lc);
    b1 = *(const float4*)(Bm + (size_t)(lr + 64) * ldb + lc);

    const int nk = Kc >> 4;
    for (int kt = 0; kt < nk; ++kt) {
        // store staged regs -> smem (transposed: As[k][m])
        As[lc + 0][lr]      = a0.x; As[lc + 1][lr]      = a0.y;
        As[lc + 2][lr]      = a0.z; As[lc + 3][lr]      = a0.w;
        As[lc + 0][lr + 64] = a1.x; As[lc + 1][lr + 64] = a1.y;
        As[lc + 2][lr + 64] = a1.z; As[lc + 3][lr + 64] = a1.w;
        Bs[lc + 0][lr]      = b0.x; Bs[lc + 1][lr]      = b0.y;
        Bs[lc + 2][lr]      = b0.z; Bs[lc + 3][lr]      = b0.w;
        Bs[lc + 0][lr + 64] = b1.x; Bs[lc + 1][lr + 64] = b1.y;
        Bs[lc + 2][lr + 64] = b1.z; Bs[lc + 3][lr + 64] = b1.w;
        __syncthreads();

        if (kt + 1 < nk) {  // prefetch next k-tile while computing
            const int k0 = (kt + 1) << 4;
            a0 = *(const float4*)(A + (size_t)lr * lda + k0 + lc);
            a1 = *(const float4*)(A + (size_t)(lr + 64) * lda + k0 + lc);
            b0 = *(const float4*)(Bm + (size_t)lr * ldb + k0 + lc);
            b1 = *(const float4*)(Bm + (size_t)(lr + 64) * ldb + k0 + lc);
        }

        #pragma unroll
        for (int c = 0; c < 16; ++c) {
            float4 af0 = *(const float4*)&As[c][ty * 8];
            float4 af1 = *(const float4*)&As[c][ty * 8 + 4];
            float4 bf0 = *(const float4*)&Bs[c][tx * 8];
            float4 bf1 = *(const float4*)&Bs[c][tx * 8 + 4];
            float av[8] = {af0.x, af0.y, af0.z, af0.w, af1.x, af1.y, af1.z, af1.w};
            float bv[8] = {bf0.x, bf0.y, bf0.z, bf0.w, bf1.x, bf1.y, bf1.z, bf1.w};
            #pragma unroll
            for (int i = 0; i < 8; ++i)
                #pragma unroll
                for (int j = 0; j < 8; ++j)
                    acc[i][j] = fmaf(av[i], bv[j], acc[i][j]);
        }
        __syncthreads();
    }
}

// =====================================================================
// Kernel 1: fused QKV projections.  y = x @ W^T + b, scattered head-major.
// grid (DM/128, B*L/128, 3)
// =====================================================================
__global__ __launch_bounds__(256, 2)
void proj_kernel(const float* __restrict__ x,
                 const float* __restrict__ Wq, const float* __restrict__ bq,
                 const float* __restrict__ Wk, const float* __restrict__ bk,
                 const float* __restrict__ Wv, const float* __restrict__ bv)
{
    const float* W; const float* bias; float* dst;
    if (blockIdx.z == 0)      { W = Wq; bias = bq; dst = g_Q; }
    else if (blockIdx.z == 1) { W = Wk; bias = bk; dst = g_K; }
    else                      { W = Wv; bias = bv; dst = g_V; }

    const float* A  = x + (size_t)blockIdx.y * 128 * DM;
    const float* Bm = W + (size_t)blockIdx.x * 128 * DM;

    float acc[8][8];
    #pragma unroll
    for (int i = 0; i < 8; ++i)
        #pragma unroll
        for (int j = 0; j < 8; ++j) acc[i][j] = 0.f;

    gemm_core_128(A, Bm, DM, DM, DM, acc);

    const int tx = threadIdx.x & 15, ty = threadIdx.x >> 4;
    const int row0 = blockIdx.y * 128 + ty * 8;
    const int col0 = blockIdx.x * 128 + tx * 8;
    #pragma unroll
    for (int i = 0; i < 8; ++i) {
        const int gi = row0 + i;
        const int b  = gi >> 11, l = gi & 2047;
        #pragma unroll
        for (int j = 0; j < 8; ++j) {
            const int o = col0 + j;
            const int h = o >> 6, d = o & 63;
            dst[(((size_t)(b * H + h) * L) + l) * DK + d] = acc[i][j] + bias[o];
        }
    }
}

// =====================================================================
// Kernel 2: S = Q K^T / 8, batched per (b,h).  grid (L/128, L/128, BH)
// =====================================================================
__global__ __launch_bounds__(256, 2)
void scores_kernel()
{
    const int bh = blockIdx.z;
    const float* A  = g_Q + (size_t)bh * L * DK + (size_t)blockIdx.y * 128 * DK;
    const float* Bm = g_K + (size_t)bh * L * DK + (size_t)blockIdx.x * 128 * DK;

    float acc[8][8];
    #pragma unroll
    for (int i = 0; i < 8; ++i)
        #pragma unroll
        for (int j = 0; j < 8; ++j) acc[i][j] = 0.f;

    gemm_core_128(A, Bm, DK, DK, DK, acc);

    float* Sh = g_S + (size_t)bh * L * L;
    const int tx = threadIdx.x & 15, ty = threadIdx.x >> 4;
    const int row0 = blockIdx.y * 128 + ty * 8;
    const int col0 = blockIdx.x * 128 + tx * 8;
    #pragma unroll
    for (int i = 0; i < 8; ++i)
        #pragma unroll
        for (int j = 0; j < 8; ++j)
            Sh[(size_t)(row0 + i) * L + (col0 + j)] = acc[i][j] * 0.125f;
}

// =====================================================================
// Kernel 3: per-row exact top-38 threshold (4-pass radix select on
// order-preserving float bits) + masked softmax + sparse AV.
// One warp per (bh,q) row; scores live in 64 regs/lane.
// =====================================================================
__device__ __forceinline__ unsigned f2key(float f)
{
    unsigned u = __float_as_uint(f);
    return u ^ (((unsigned)((int)u >> 31)) | 0x80000000u);
}

__global__ __launch_bounds__(256)
void topk_av_kernel()
{
    __shared__ int hist[8][256];
    const int w    = threadIdx.x >> 5;
    const int lane = threadIdx.x & 31;
    const int row  = blockIdx.x * 8 + w;      // 0 .. BH*L-1
    const int bh   = row >> 11;
    const int q    = row & 2047;

    const float* srow = g_S + (size_t)row * L;

    float v[64];
    float m = -1e30f;
    #pragma unroll
    for (int t = 0; t < 64; ++t) {
        v[t] = srow[t * 32 + lane];
        m = fmaxf(m, v[t]);
    }
    #pragma unroll
    for (int off = 16; off; off >>= 1)
        m = fmaxf(m, __shfl_xor_sync(FULLMASK, m, off));

    // ---- exact 38th-largest via 8-bit radix passes ----
    unsigned prefix = 0, pmask = 0;
    int kneed = U;
    #pragma unroll
    for (int pass = 0; pass < 4; ++pass) {
        const int shift = 24 - pass * 8;
        for (int i = lane; i < 256; i += 32) hist[w][i] = 0;
        __syncwarp();
        #pragma unroll
        for (int t = 0; t < 64; ++t) {
            const unsigned kk = f2key(v[t]);
            if ((kk & pmask) == prefix)
                atomicAdd(&hist[w][(kk >> shift) & 255], 1);
        }
        __syncwarp();
        // group sums: lane owns bins [8*lane, 8*lane+7]
        int s = 0;
        #pragma unroll
        for (int i = 0; i < 8; ++i) s += hist[w][lane * 8 + i];
        // suffix sums over groups: Us(l) = sum_{g>=l} s(g)
        int Us = s;
        #pragma unroll
        for (int off = 1; off < 32; off <<= 1) {
            const int o2 = __shfl_down_sync(FULLMASK, Us, off);
            if (lane + off < 32) Us += o2;
        }
        const unsigned bal = __ballot_sync(FULLMASK, Us >= kneed);
        const int gstar = 31 - __clz(bal);
        const int Ug = __shfl_sync(FULLMASK, Us, gstar);
        const int sg = __shfl_sync(FULLMASK, s,  gstar);
        int run = Ug - sg;                 // suffix count below this group
        int digit = 0, above = 0;
        #pragma unroll
        for (int i = 7; i >= 0; --i) {
            const int hcnt = hist[w][gstar * 8 + i];
            if (run + hcnt >= kneed && run < kneed) { digit = i; above = run; }
            run += hcnt;
        }
        kneed  -= above;
        prefix |= (unsigned)(gstar * 8 + digit) << shift;
        pmask  |= 0xFFu << shift;
        __syncwarp();
    }
    const unsigned T = prefix;   // exact bit pattern of the 38th-largest score

    // ---- masked softmax weights (unnormalized), Z ----
    float Z = 0.f;
    #pragma unroll
    for (int t = 0; t < 64; ++t) {
        const float e = (f2key(v[t]) >= T) ? __expf(v[t] - m) : 0.f;
        v[t] = e;
        Z += e;
    }
    #pragma unroll
    for (int off = 16; off; off >>= 1)
        Z += __shfl_xor_sync(FULLMASK, Z, off);
    const float invZ = 1.f / Z;

    // ---- sparse AV: gather the ~38 selected V rows ----
    const float* Vh = g_V + (size_t)bh * L * DK;
    float o0 = 0.f, o1 = 0.f;   // out dims: lane, lane+32
    #pragma unroll
    for (int t = 0; t < 64; ++t) {
        unsigned bal = __ballot_sync(FULLMASK, v[t] != 0.f);
        while (bal) {
            const int src = __ffs(bal) - 1;
            bal &= bal - 1;
            const float wj = __shfl_sync(FULLMASK, v[t], src);
            const float* vr = Vh + (size_t)(t * 32 + src) * DK;
            o0 += wj * vr[lane];
            o1 += wj * vr[lane + 32];
        }
    }

    const int b = bh >> 3, h = bh & 7;
    float* ao = g_AO + (size_t)(b * L + q) * DM + h * DK;
    ao[lane]      = o0 * invZ;
    ao[lane + 32] = o1 * invZ;
}

// =====================================================================
// Kernel 4: out = AO @ Wo^T + bo.  grid (DM/128, B*L/128)
// =====================================================================
__global__ __launch_bounds__(256, 2)
void outproj_kernel(const float* __restrict__ Wo, const float* __restrict__ bo,
                    float* __restrict__ out)
{
    const float* A  = g_AO + (size_t)blockIdx.y * 128 * DM;
    const float* Bm = Wo   + (size_t)blockIdx.x * 128 * DM;

    float acc[8][8];
    #pragma unroll
    for (int i = 0; i < 8; ++i)
        #pragma unroll
        for (int j = 0; j < 8; ++j) acc[i][j] = 0.f;

    gemm_core_128(A, Bm, DM, DM, DM, acc);

    const int tx = threadIdx.x & 15, ty = threadIdx.x >> 4;
    const int row0 = blockIdx.y * 128 + ty * 8;
    const int col0 = blockIdx.x * 128 + tx * 8;
    #pragma unroll
    for (int i = 0; i < 8; ++i)
        #pragma unroll
        for (int j = 0; j < 8; ++j)
            out[(size_t)(row0 + i) * DM + (col0 + j)] = acc[i][j] + bo[col0 + j];
}

// =====================================================================
extern "C" void kernel_launch(void* const* d_in, const int* in_sizes, int n_in,
                              void* d_out, int out_size)
{
    const float* x  = (const float*)d_in[0];
    const float* Wq = (const float*)d_in[1];
    const float* bq = (const float*)d_in[2];
    const float* Wk = (const float*)d_in[3];
    const float* bk = (const float*)d_in[4];
    const float* Wv = (const float*)d_in[5];
    const float* bv = (const float*)d_in[6];
    const float* Wo = (const float*)d_in[7];
    const float* bo = (const float*)d_in[8];
    float* out = (float*)d_out;

    dim3 blk(256);
    proj_kernel<<<dim3(DM / 128, (Bb * L) / 128, 3), blk>>>(x, Wq, bq, Wk, bk, Wv, bv);
    scores_kernel<<<dim3(L / 128, L / 128, BH), blk>>>();
    topk_av_kernel<<<(BH * L) / 8, blk>>>();
    outproj_kernel<<<dim3(DM / 128, (Bb * L) / 128), blk>>>(Wo, bo, out);
}

// round 6
// speedup vs baseline: 1.5062x; 1.5062x over previous
#include <cuda_runtime.h>

#define FULLMASK 0xFFFFFFFFu

static constexpr int Bb = 2;
static constexpr int L  = 2048;
static constexpr int DM = 512;
static constexpr int H  = 8;
static constexpr int DK = 64;
static constexpr int U  = 38;     // int(5 * ln(2048)) = 38
static constexpr int BH = Bb * H; // 16

// ---------------- scratch (static device globals; no allocation) ----------------
__device__ float g_Q[(size_t)Bb * H * L * DK];     // 8 MB  head-major [bh][l][d]
__device__ float g_K[(size_t)Bb * H * L * DK];     // 8 MB
__device__ float g_V[(size_t)Bb * H * L * DK];     // 8 MB
__device__ float g_S[(size_t)Bb * H * L * L];      // 256 MB scores [bh][q][k]
__device__ float g_AO[(size_t)Bb * L * DM];        // 8 MB  attention out [b][l][dm]

// ---------------- packed fp32x2 helpers (sm_103a FFMA2) ----------------
__device__ __forceinline__ unsigned long long pk2(float lo, float hi)
{
    unsigned long long r;
    asm("mov.b64 %0, {%1, %2};" : "=l"(r) : "f"(lo), "f"(hi));
    return r;
}
__device__ __forceinline__ void upk2(unsigned long long p, float& lo, float& hi)
{
    asm("mov.b64 {%0, %1}, %2;" : "=f"(lo), "=f"(hi) : "l"(p));
}
__device__ __forceinline__ void ffma2(unsigned long long& d,
                                      unsigned long long a, unsigned long long b)
{
    asm("fma.rn.f32x2 %0, %1, %2, %0;" : "+l"(d) : "l"(a), "l"(b));
}

// =====================================================================
// Shared SGEMM core: C(128x128) += A(128xK) * B(128xK)^T  (both K-major)
// 256 threads, split 8x8 microtile (4+4 rows/cols, 64 apart -> conflict-
// free LDS.128), BK=16, register-staged pipeline, packed FFMA2 math.
// Thread (tx,ty) owns rows {ty*4..+3, 64+ty*4..+3} x cols {tx*4..+3,
// 64+tx*4..+3}.  acc[i][j]: i/j index into those ordered sets.
// =====================================================================
__device__ __forceinline__ void gemm_core_128(
    const float* __restrict__ A, const float* __restrict__ Bm,
    int lda, int ldb, int Kc, float (&acc)[8][8])
{
    __shared__ float As[16][132];
    __shared__ float Bs[16][132];

    const int tid = threadIdx.x;
    const int tx  = tid & 15;
    const int ty  = tid >> 4;
    const int lr  = tid >> 2;          // 0..63  (tile row; +64 for second half)
    const int lc  = (tid & 3) << 2;    // 0,4,8,12 (k-column within BK)

    unsigned long long acc2[8][4];
    #pragma unroll
    for (int i = 0; i < 8; ++i)
        #pragma unroll
        for (int j = 0; j < 4; ++j) acc2[i][j] = 0ULL;

    float4 a0, a1, b0, b1;
    // prologue: stage k-tile 0
    a0 = *(const float4*)(A + (size_t)lr * lda + lc);
    a1 = *(const float4*)(A + (size_t)(lr + 64) * lda + lc);
    b0 = *(const float4*)(Bm + (size_t)lr * ldb + lc);
    b1 = *(const float4*)(Bm + (size_t)(lr + 64) * ldb + lc);

    const int nk = Kc >> 4;
    for (int kt = 0; kt < nk; ++kt) {
        // store staged regs -> smem (transposed: As[k][m])
        As[lc + 0][lr]      = a0.x; As[lc + 1][lr]      = a0.y;
        As[lc + 2][lr]      = a0.z; As[lc + 3][lr]      = a0.w;
        As[lc + 0][lr + 64] = a1.x; As[lc + 1][lr + 64] = a1.y;
        As[lc + 2][lr + 64] = a1.z; As[lc + 3][lr + 64] = a1.w;
        Bs[lc + 0][lr]      = b0.x; Bs[lc + 1][lr]      = b0.y;
        Bs[lc + 2][lr]      = b0.z; Bs[lc + 3][lr]      = b0.w;
        Bs[lc + 0][lr + 64] = b1.x; Bs[lc + 1][lr + 64] = b1.y;
        Bs[lc + 2][lr + 64] = b1.z; Bs[lc + 3][lr + 64] = b1.w;
        __syncthreads();

        if (kt + 1 < nk) {  // prefetch next k-tile while computing
            const int k0 = (kt + 1) << 4;
            a0 = *(const float4*)(A + (size_t)lr * lda + k0 + lc);
            a1 = *(const float4*)(A + (size_t)(lr + 64) * lda + k0 + lc);
            b0 = *(const float4*)(Bm + (size_t)lr * ldb + k0 + lc);
            b1 = *(const float4*)(Bm + (size_t)(lr + 64) * ldb + k0 + lc);
        }

        #pragma unroll
        for (int c = 0; c < 16; ++c) {
            // conflict-free: addresses stride 16B across tx/ty within a phase
            float4 af0 = *(const float4*)&As[c][ty * 4];
            float4 af1 = *(const float4*)&As[c][64 + ty * 4];
            float4 bf0 = *(const float4*)&Bs[c][tx * 4];
            float4 bf1 = *(const float4*)&Bs[c][64 + tx * 4];

            unsigned long long bp[4], ap[8];
            bp[0] = pk2(bf0.x, bf0.y); bp[1] = pk2(bf0.z, bf0.w);
            bp[2] = pk2(bf1.x, bf1.y); bp[3] = pk2(bf1.z, bf1.w);
            ap[0] = pk2(af0.x, af0.x); ap[1] = pk2(af0.y, af0.y);
            ap[2] = pk2(af0.z, af0.z); ap[3] = pk2(af0.w, af0.w);
            ap[4] = pk2(af1.x, af1.x); ap[5] = pk2(af1.y, af1.y);
            ap[6] = pk2(af1.z, af1.z); ap[7] = pk2(af1.w, af1.w);

            #pragma unroll
            for (int i = 0; i < 8; ++i)
                #pragma unroll
                for (int jj = 0; jj < 4; ++jj)
                    ffma2(acc2[i][jj], ap[i], bp[jj]);
        }
        __syncthreads();
    }

    #pragma unroll
    for (int i = 0; i < 8; ++i)
        #pragma unroll
        for (int jj = 0; jj < 4; ++jj)
            upk2(acc2[i][jj], acc[i][2 * jj], acc[i][2 * jj + 1]);
}

// split-microtile index helpers
__device__ __forceinline__ int mt_ofs(int t4, int i)   // t4 = tx or ty
{
    return (i < 4) ? (t4 * 4 + i) : (64 + t4 * 4 + (i - 4));
}

// =====================================================================
// Kernel 1: fused QKV projections.  y = x @ W^T + b, scattered head-major.
// grid (DM/128, B*L/128, 3)
// =====================================================================
__global__ __launch_bounds__(256)
void proj_kernel(const float* __restrict__ x,
                 const float* __restrict__ Wq, const float* __restrict__ bq,
                 const float* __restrict__ Wk, const float* __restrict__ bk,
                 const float* __restrict__ Wv, const float* __restrict__ bv)
{
    const float* W; const float* bias; float* dst;
    if (blockIdx.z == 0)      { W = Wq; bias = bq; dst = g_Q; }
    else if (blockIdx.z == 1) { W = Wk; bias = bk; dst = g_K; }
    else                      { W = Wv; bias = bv; dst = g_V; }

    const float* A  = x + (size_t)blockIdx.y * 128 * DM;
    const float* Bm = W + (size_t)blockIdx.x * 128 * DM;

    float acc[8][8];
    gemm_core_128(A, Bm, DM, DM, DM, acc);

    const int tx = threadIdx.x & 15, ty = threadIdx.x >> 4;
    #pragma unroll
    for (int i = 0; i < 8; ++i) {
        const int gi = blockIdx.y * 128 + mt_ofs(ty, i);
        const int b  = gi >> 11, l = gi & 2047;
        #pragma unroll
        for (int j = 0; j < 8; ++j) {
            const int o = blockIdx.x * 128 + mt_ofs(tx, j);
            const int h = o >> 6, d = o & 63;
            dst[(((size_t)(b * H + h) * L) + l) * DK + d] = acc[i][j] + bias[o];
        }
    }
}

// =====================================================================
// Kernel 2: S = Q K^T / 8, batched per (b,h).  grid (L/128, L/128, BH)
// =====================================================================
__global__ __launch_bounds__(256)
void scores_kernel()
{
    const int bh = blockIdx.z;
    const float* A  = g_Q + (size_t)bh * L * DK + (size_t)blockIdx.y * 128 * DK;
    const float* Bm = g_K + (size_t)bh * L * DK + (size_t)blockIdx.x * 128 * DK;

    float acc[8][8];
    gemm_core_128(A, Bm, DK, DK, DK, acc);

    float* Sh = g_S + (size_t)bh * L * L;
    const int tx = threadIdx.x & 15, ty = threadIdx.x >> 4;
    #pragma unroll
    for (int i = 0; i < 8; ++i) {
        const int r = blockIdx.y * 128 + mt_ofs(ty, i);
        #pragma unroll
        for (int j = 0; j < 8; ++j) {
            const int cc = blockIdx.x * 128 + mt_ofs(tx, j);
            Sh[(size_t)r * L + cc] = acc[i][j] * 0.125f;
        }
    }
}

// =====================================================================
// Kernel 3: per-row exact top-38 threshold via bit-by-bit count search
// (no atomics, no smem) + masked softmax + sparse AV.
// One warp per (bh,q) row; 2048 scores live as 64 keys/lane.
// Value index mapping: idx = (t>>2)*128 + lane*4 + (t&3).
// =====================================================================
__device__ __forceinline__ unsigned f2key(float f)
{
    unsigned u = __float_as_uint(f);
    return u ^ (((unsigned)((int)u >> 31)) | 0x80000000u);
}
__device__ __forceinline__ float key2f(unsigned k)
{
    unsigned u = (k & 0x80000000u) ? (k ^ 0x80000000u) : ~k;
    return __uint_as_float(u);
}

__global__ __launch_bounds__(256)
void topk_av_kernel()
{
    const int lane = threadIdx.x & 31;
    const int row  = blockIdx.x * 8 + (threadIdx.x >> 5);  // 0 .. BH*L-1
    const int bh   = row >> 11;
    const int q    = row & 2047;

    const float* srow = g_S + (size_t)row * L;

    unsigned u[64];
    unsigned mk = 0;
    #pragma unroll
    for (int c = 0; c < 16; ++c) {
        const float4 f = *(const float4*)(srow + c * 128 + lane * 4);
        u[c * 4 + 0] = f2key(f.x);
        u[c * 4 + 1] = f2key(f.y);
        u[c * 4 + 2] = f2key(f.z);
        u[c * 4 + 3] = f2key(f.w);
        mk = max(mk, max(max(u[c * 4], u[c * 4 + 1]), max(u[c * 4 + 2], u[c * 4 + 3])));
    }
    #pragma unroll
    for (int off = 16; off; off >>= 1)
        mk = max(mk, __shfl_xor_sync(FULLMASK, mk, off));
    const float m = key2f(mk);

    // ---- exact 38th-largest key: greedy bit-by-bit with early exit ----
    unsigned T = 0;
    bool found = false;
    for (int b = 31; b >= 0 && !found; --b) {
        const unsigned cand = T | (1u << b);
        int cnt = 0;
        #pragma unroll
        for (int t = 0; t < 64; ++t) cnt += (u[t] >= cand);
        #pragma unroll
        for (int off = 16; off; off >>= 1)
            cnt += __shfl_xor_sync(FULLMASK, cnt, off);
        if (cnt >= U) T = cand;
        if (cnt == U) {
            // exact top-38 set fixed: threshold = min of selected keys
            unsigned mn = 0xFFFFFFFFu;
            #pragma unroll
            for (int t = 0; t < 64; ++t)
                if (u[t] >= cand) mn = min(mn, u[t]);
            #pragma unroll
            for (int off = 16; off; off >>= 1)
                mn = min(mn, __shfl_xor_sync(FULLMASK, mn, off));
            T = mn;
            found = true;
        }
    }

    // ---- masked softmax weights (unnormalized); reuse key regs ----
    float Z = 0.f;
    #pragma unroll
    for (int t = 0; t < 64; ++t) {
        float e = 0.f;
        if (u[t] >= T) e = __expf(key2f(u[t]) - m);   // MUFU only where selected
        Z += e;
        u[t] = __float_as_uint(e);
    }
    #pragma unroll
    for (int off = 16; off; off >>= 1)
        Z += __shfl_xor_sync(FULLMASK, Z, off);
    const float invZ = 1.f / Z;

    // ---- sparse AV: gather the ~38 selected V rows ----
    const float* Vh = g_V + (size_t)bh * L * DK;
    float o0 = 0.f, o1 = 0.f;   // out dims: lane, lane+32
    #pragma unroll
    for (int t = 0; t < 64; ++t) {
        const float ww = __uint_as_float(u[t]);
        unsigned bal = __ballot_sync(FULLMASK, ww != 0.f);
        while (bal) {
            const int src = __ffs(bal) - 1;
            bal &= bal - 1;
            const float wj = __shfl_sync(FULLMASK, ww, src);
            const int kidx = (t >> 2) * 128 + src * 4 + (t & 3);
            const float* vr = Vh + (size_t)kidx * DK;
            o0 += wj * vr[lane];
            o1 += wj * vr[lane + 32];
        }
    }

    const int b = bh >> 3, h = bh & 7;
    float* ao = g_AO + (size_t)(b * L + q) * DM + h * DK;
    ao[lane]      = o0 * invZ;
    ao[lane + 32] = o1 * invZ;
}

// =====================================================================
// Kernel 4: out = AO @ Wo^T + bo.  grid (DM/128, B*L/128)
// =====================================================================
__global__ __launch_bounds__(256)
void outproj_kernel(const float* __restrict__ Wo, const float* __restrict__ bo,
                    float* __restrict__ out)
{
    const float* A  = g_AO + (size_t)blockIdx.y * 128 * DM;
    const float* Bm = Wo   + (size_t)blockIdx.x * 128 * DM;

    float acc[8][8];
    gemm_core_128(A, Bm, DM, DM, DM, acc);

    const int tx = threadIdx.x & 15, ty = threadIdx.x >> 4;
    #pragma unroll
    for (int i = 0; i < 8; ++i) {
        const int r = blockIdx.y * 128 + mt_ofs(ty, i);
        #pragma unroll
        for (int j = 0; j < 8; ++j) {
            const int cc = blockIdx.x * 128 + mt_ofs(tx, j);
            out[(size_t)r * DM + cc] = acc[i][j] + bo[cc];
        }
    }
}

// =====================================================================
extern "C" void kernel_launch(void* const* d_in, const int* in_sizes, int n_in,
                              void* d_out, int out_size)
{
    const float* x  = (const float*)d_in[0];
    const float* Wq = (const float*)d_in[1];
    const float* bq = (const float*)d_in[2];
    const float* Wk = (const float*)d_in[3];
    const float* bk = (const float*)d_in[4];
    const float* Wv = (const float*)d_in[5];
    const float* bv = (const float*)d_in[6];
    const float* Wo = (const float*)d_in[7];
    const float* bo = (const float*)d_in[8];
    float* out = (float*)d_out;

    dim3 blk(256);
    proj_kernel<<<dim3(DM / 128, (Bb * L) / 128, 3), blk>>>(x, Wq, bq, Wk, bk, Wv, bv);
    scores_kernel<<<dim3(L / 128, L / 128, BH), blk>>>();
    topk_av_kernel<<<(BH * L) / 8, blk>>>();
    outproj_kernel<<<dim3(DM / 128, (Bb * L) / 128), blk>>>(Wo, bo, out);
}

// round 8
// speedup vs baseline: 1.6361x; 1.0863x over previous
#include <cuda_runtime.h>

#define FULLMASK 0xFFFFFFFFu

static constexpr int Bb = 2;
static constexpr int L  = 2048;
static constexpr int DM = 512;
static constexpr int H  = 8;
static constexpr int DK = 64;
static constexpr int U  = 38;     // int(5 * ln(2048)) = 38
static constexpr int BH = Bb * H; // 16

// ---------------- scratch (static device globals; no allocation) ----------------
__device__ float g_Q[(size_t)Bb * H * L * DK];     // 8 MB  head-major [bh][l][d]
__device__ float g_K[(size_t)Bb * H * L * DK];     // 8 MB
__device__ float g_V[(size_t)Bb * H * L * DK];     // 8 MB
__device__ float g_S[(size_t)Bb * H * L * L];      // 256 MB scores [bh][q][k]
__device__ float g_AO[(size_t)Bb * L * DM];        // 8 MB  attention out [b][l][dm]

// ---------------- packed fp32x2 helpers (sm_103a FFMA2) ----------------
__device__ __forceinline__ void upk2(unsigned long long p, float& lo, float& hi)
{
    asm("mov.b64 {%0, %1}, %2;" : "=f"(lo), "=f"(hi) : "l"(p));
}
__device__ __forceinline__ void ffma2(unsigned long long& d,
                                      unsigned long long a, unsigned long long b)
{
    asm("fma.rn.f32x2 %0, %1, %2, %0;" : "+l"(d) : "l"(a), "l"(b));
}

// =====================================================================
// Shared SGEMM core: C(128x128) += A(128xK) * B(128xK)^T  (both K-major)
// 256 threads, split 8x8 microtile (4+4 rows/cols, 64 apart), BK=16,
// register-staged pipeline, packed FFMA2.
// A is stored DUPLICATED in smem: As2[k][2m] = As2[k][2m+1] = A[m][k],
// so LDS.128 delivers (a,a) b64 pairs directly -> zero pack MOVs.
// B pairs come straight from float4 LDS.128 register pairs.
// =====================================================================
static constexpr int ASTRIDE = 268;   // floats; mult of 4 (LDS.128 align), 4*268 % 32 != 0

__device__ __forceinline__ void gemm_core_128(
    const float* __restrict__ A, const float* __restrict__ Bm,
    int lda, int ldb, int Kc, float (&acc)[8][8])
{
    __shared__ float As2[16][ASTRIDE];   // duplicated A
    __shared__ float Bs[16][132];

    const int tid = threadIdx.x;
    const int tx  = tid & 15;
    const int ty  = tid >> 4;
    const int lr  = tid >> 2;          // 0..63  (tile row; +64 for second half)
    const int lc  = (tid & 3) << 2;    // 0,4,8,12 (k-column within BK)

    unsigned long long acc2[8][4];
    #pragma unroll
    for (int i = 0; i < 8; ++i)
        #pragma unroll
        for (int j = 0; j < 4; ++j) acc2[i][j] = 0ULL;

    float4 a0, a1, b0, b1;
    // prologue: stage k-tile 0
    a0 = *(const float4*)(A + (size_t)lr * lda + lc);
    a1 = *(const float4*)(A + (size_t)(lr + 64) * lda + lc);
    b0 = *(const float4*)(Bm + (size_t)lr * ldb + lc);
    b1 = *(const float4*)(Bm + (size_t)(lr + 64) * ldb + lc);

    const int nk = Kc >> 4;
    for (int kt = 0; kt < nk; ++kt) {
        // store staged regs -> smem (A duplicated, transposed: As2[k][2m,2m+1])
        *(float2*)&As2[lc + 0][2 * lr]        = make_float2(a0.x, a0.x);
        *(float2*)&As2[lc + 1][2 * lr]        = make_float2(a0.y, a0.y);
        *(float2*)&As2[lc + 2][2 * lr]        = make_float2(a0.z, a0.z);
        *(float2*)&As2[lc + 3][2 * lr]        = make_float2(a0.w, a0.w);
        *(float2*)&As2[lc + 0][2 * (lr + 64)] = make_float2(a1.x, a1.x);
        *(float2*)&As2[lc + 1][2 * (lr + 64)] = make_float2(a1.y, a1.y);
        *(float2*)&As2[lc + 2][2 * (lr + 64)] = make_float2(a1.z, a1.z);
        *(float2*)&As2[lc + 3][2 * (lr + 64)] = make_float2(a1.w, a1.w);
        Bs[lc + 0][lr]      = b0.x; Bs[lc + 1][lr]      = b0.y;
        Bs[lc + 2][lr]      = b0.z; Bs[lc + 3][lr]      = b0.w;
        Bs[lc + 0][lr + 64] = b1.x; Bs[lc + 1][lr + 64] = b1.y;
        Bs[lc + 2][lr + 64] = b1.z; Bs[lc + 3][lr + 64] = b1.w;
        __syncthreads();

        if (kt + 1 < nk) {  // prefetch next k-tile while computing
            const int k0 = (kt + 1) << 4;
            a0 = *(const float4*)(A + (size_t)lr * lda + k0 + lc);
            a1 = *(const float4*)(A + (size_t)(lr + 64) * lda + k0 + lc);
            b0 = *(const float4*)(Bm + (size_t)lr * ldb + k0 + lc);
            b1 = *(const float4*)(Bm + (size_t)(lr + 64) * ldb + k0 + lc);
        }

        #pragma unroll
        for (int c = 0; c < 16; ++c) {
            const unsigned long long* ar =
                (const unsigned long long*)&As2[c][0];   // b64 index m = row m
            ulonglong2 A0 = *(const ulonglong2*)(ar + ty * 4);
            ulonglong2 A1 = *(const ulonglong2*)(ar + ty * 4 + 2);
            ulonglong2 A2 = *(const ulonglong2*)(ar + 64 + ty * 4);
            ulonglong2 A3 = *(const ulonglong2*)(ar + 64 + ty * 4 + 2);
            ulonglong2 B0 = *(const ulonglong2*)&Bs[c][tx * 4];
            ulonglong2 B1 = *(const ulonglong2*)&Bs[c][64 + tx * 4];

            unsigned long long ap[8] = {A0.x, A0.y, A1.x, A1.y,
                                        A2.x, A2.y, A3.x, A3.y};
            unsigned long long bp[4] = {B0.x, B0.y, B1.x, B1.y};

            #pragma unroll
            for (int i = 0; i < 8; ++i)
                #pragma unroll
                for (int jj = 0; jj < 4; ++jj)
                    ffma2(acc2[i][jj], ap[i], bp[jj]);
        }
        __syncthreads();
    }

    #pragma unroll
    for (int i = 0; i < 8; ++i)
        #pragma unroll
        for (int jj = 0; jj < 4; ++jj)
            upk2(acc2[i][jj], acc[i][2 * jj], acc[i][2 * jj + 1]);
}

// split-microtile index helper
__device__ __forceinline__ int mt_ofs(int t4, int i)
{
    return (i < 4) ? (t4 * 4 + i) : (64 + t4 * 4 + (i - 4));
}

// =====================================================================
// Kernel 1: fused QKV projections.  y = x @ W^T + b, scattered head-major.
// grid (DM/128, B*L/128, 3)
// =====================================================================
__global__ __launch_bounds__(256)
void proj_kernel(const float* __restrict__ x,
                 const float* __restrict__ Wq, const float* __restrict__ bq,
                 const float* __restrict__ Wk, const float* __restrict__ bk,
                 const float* __restrict__ Wv, const float* __restrict__ bv)
{
    const float* W; const float* bias; float* dst;
    if (blockIdx.z == 0)      { W = Wq; bias = bq; dst = g_Q; }
    else if (blockIdx.z == 1) { W = Wk; bias = bk; dst = g_K; }
    else                      { W = Wv; bias = bv; dst = g_V; }

    const float* A  = x + (size_t)blockIdx.y * 128 * DM;
    const float* Bm = W + (size_t)blockIdx.x * 128 * DM;

    float acc[8][8];
    gemm_core_128(A, Bm, DM, DM, DM, acc);

    const int tx = threadIdx.x & 15, ty = threadIdx.x >> 4;
    #pragma unroll
    for (int i = 0; i < 8; ++i) {
        const int gi = blockIdx.y * 128 + mt_ofs(ty, i);
        const int b  = gi >> 11, l = gi & 2047;
        #pragma unroll
        for (int jh = 0; jh < 2; ++jh) {
            const int o = blockIdx.x * 128 + (jh ? 64 + tx * 4 : tx * 4);
            const int h = o >> 6, d = o & 63;  // 4-chunk never crosses a head
            float4 r = make_float4(acc[i][jh * 4 + 0] + bias[o + 0],
                                   acc[i][jh * 4 + 1] + bias[o + 1],
                                   acc[i][jh * 4 + 2] + bias[o + 2],
                                   acc[i][jh * 4 + 3] + bias[o + 3]);
            *(float4*)&dst[(((size_t)(b * H + h) * L) + l) * DK + d] = r;
        }
    }
}

// =====================================================================
// Kernel 2: S = Q K^T / 8, batched per (b,h).  grid (L/128, L/128, BH)
// =====================================================================
__global__ __launch_bounds__(256)
void scores_kernel()
{
    const int bh = blockIdx.z;
    const float* A  = g_Q + (size_t)bh * L * DK + (size_t)blockIdx.y * 128 * DK;
    const float* Bm = g_K + (size_t)bh * L * DK + (size_t)blockIdx.x * 128 * DK;

    float acc[8][8];
    gemm_core_128(A, Bm, DK, DK, DK, acc);

    float* Sh = g_S + (size_t)bh * L * L;
    const int tx = threadIdx.x & 15, ty = threadIdx.x >> 4;
    #pragma unroll
    for (int i = 0; i < 8; ++i) {
        const int r = blockIdx.y * 128 + mt_ofs(ty, i);
        #pragma unroll
        for (int jh = 0; jh < 2; ++jh) {
            const int cc = blockIdx.x * 128 + (jh ? 64 + tx * 4 : tx * 4);
            float4 v = make_float4(acc[i][jh * 4 + 0] * 0.125f,
                                   acc[i][jh * 4 + 1] * 0.125f,
                                   acc[i][jh * 4 + 2] * 0.125f,
                                   acc[i][jh * 4 + 3] * 0.125f);
            __stcs((float4*)&Sh[(size_t)r * L + cc], v);   // stream: read once later
        }
    }
}

// =====================================================================
// Kernel 3: per-row exact top-38 threshold (bit search + REDUX) +
// masked softmax + compacted batched AV.  One warp per (bh,q) row.
// Value index mapping: idx = (t>>2)*128 + lane*4 + (t&3).
// =====================================================================
__device__ __forceinline__ unsigned f2key(float f)
{
    unsigned u = __float_as_uint(f);
    return u ^ (((unsigned)((int)u >> 31)) | 0x80000000u);
}
__device__ __forceinline__ float key2f(unsigned k)
{
    unsigned u = (k & 0x80000000u) ? (k ^ 0x80000000u) : ~k;
    return __uint_as_float(u);
}

__global__ __launch_bounds__(256)
void topk_av_kernel()
{
    __shared__ float          s_w[8][64];
    __shared__ unsigned short s_i[8][64];

    const int w    = threadIdx.x >> 5;
    const int lane = threadIdx.x & 31;
    const int row  = blockIdx.x * 8 + w;      // 0 .. BH*L-1
    const int bh   = row >> 11;
    const int q    = row & 2047;

    const float* srow = g_S + (size_t)row * L;

    unsigned u[64];
    unsigned mk = 0;
    #pragma unroll
    for (int c = 0; c < 16; ++c) {
        const float4 f = __ldcs((const float4*)(srow + c * 128 + lane * 4));
        u[c * 4 + 0] = f2key(f.x);
        u[c * 4 + 1] = f2key(f.y);
        u[c * 4 + 2] = f2key(f.z);
        u[c * 4 + 3] = f2key(f.w);
        mk = max(mk, max(max(u[c * 4], u[c * 4 + 1]), max(u[c * 4 + 2], u[c * 4 + 3])));
    }
    mk = __reduce_max_sync(FULLMASK, mk);
    const float m = key2f(mk);

    // ---- exact 38th-largest key: greedy bit-by-bit, REDUX reductions ----
    unsigned T = 0;
    bool found = false;
    for (int b = 31; b >= 0 && !found; --b) {
        const unsigned cand = T | (1u << b);
        int cnt = 0;
        #pragma unroll
        for (int t = 0; t < 64; ++t) cnt += (u[t] >= cand);
        cnt = __reduce_add_sync(FULLMASK, cnt);
        if (cnt >= U) T = cand;
        if (cnt == U) found = true;
    }
    {   // exact threshold = min of selected keys (handles early exit + ties)
        unsigned mn = 0xFFFFFFFFu;
        #pragma unroll
        for (int t = 0; t < 64; ++t)
            if (u[t] >= T) mn = min(mn, u[t]);
        T = __reduce_min_sync(FULLMASK, mn);
    }

    // ---- masked softmax weights + warp compaction into smem lists ----
    float Z = 0.f;
    int base = 0;
    #pragma unroll
    for (int t = 0; t < 64; ++t) {
        const bool sel = (u[t] >= T);
        float e = 0.f;
        if (sel) e = __expf(key2f(u[t]) - m);
        Z += e;
        const unsigned bal = __ballot_sync(FULLMASK, sel);
        if (sel) {
            const int pos = base + __popc(bal & ((1u << lane) - 1u));
            if (pos < 64) {
                s_w[w][pos] = e;
                s_i[w][pos] = (unsigned short)((t >> 2) * 128 + lane * 4 + (t & 3));
            }
        }
        base += __popc(bal);
    }
    const int nsel = min(base, 64);
    #pragma unroll
    for (int off = 16; off; off >>= 1)
        Z += __shfl_xor_sync(FULLMASK, Z, off);
    const float invZ = 1.f / Z;
    __syncwarp();

    // ---- batched sparse AV over compacted list (MLP ~8) ----
    const float* Vh = g_V + (size_t)bh * L * DK;
    float o0 = 0.f, o1 = 0.f;
    int j = 0;
    for (; j + 4 <= nsel; j += 4) {
        const float w0 = s_w[w][j],     w1 = s_w[w][j + 1];
        const float w2 = s_w[w][j + 2], w3 = s_w[w][j + 3];
        const float* v0 = Vh + (size_t)s_i[w][j]     * DK;
        const float* v1 = Vh + (size_t)s_i[w][j + 1] * DK;
        const float* v2 = Vh + (size_t)s_i[w][j + 2] * DK;
        const float* v3 = Vh + (size_t)s_i[w][j + 3] * DK;
        const float a0 = v0[lane], b0v = v0[lane + 32];
        const float a1 = v1[lane], b1v = v1[lane + 32];
        const float a2 = v2[lane], b2v = v2[lane + 32];
        const float a3 = v3[lane], b3v = v3[lane + 32];
        o0 += w0 * a0 + w1 * a1 + w2 * a2 + w3 * a3;
        o1 += w0 * b0v + w1 * b1v + w2 * b2v + w3 * b3v;
    }
    for (; j < nsel; ++j) {
        const float wj = s_w[w][j];
        const float* vr = Vh + (size_t)s_i[w][j] * DK;
        o0 += wj * vr[lane];
        o1 += wj * vr[lane + 32];
    }

    const int b = bh >> 3, h = bh & 7;
    float* ao = g_AO + (size_t)(b * L + q) * DM + h * DK;
    ao[lane]      = o0 * invZ;
    ao[lane + 32] = o1 * invZ;
}

// =====================================================================
// Kernel 4: out = AO @ Wo^T + bo.  grid (DM/128, B*L/128)
// =====================================================================
__global__ __launch_bounds__(256)
void outproj_kernel(const float* __restrict__ Wo, const float* __restrict__ bo,
                    float* __restrict__ out)
{
    const float* A  = g_AO + (size_t)blockIdx.y * 128 * DM;
    const float* Bm = Wo   + (size_t)blockIdx.x * 128 * DM;

    float acc[8][8];
    gemm_core_128(A, Bm, DM, DM, DM, acc);

    const int tx = threadIdx.x & 15, ty = threadIdx.x >> 4;
    #pragma unroll
    for (int i = 0; i < 8; ++i) {
        const int r = blockIdx.y * 128 + mt_ofs(ty, i);
        #pragma unroll
        for (int jh = 0; jh < 2; ++jh) {
            const int cc = blockIdx.x * 128 + (jh ? 64 + tx * 4 : tx * 4);
            float4 v = make_float4(acc[i][jh * 4 + 0] + bo[cc + 0],
                                   acc[i][jh * 4 + 1] + bo[cc + 1],
                                   acc[i][jh * 4 + 2] + bo[cc + 2],
                                   acc[i][jh * 4 + 3] + bo[cc + 3]);
            *(float4*)&out[(size_t)r * DM + cc] = v;
        }
    }
}

// =====================================================================
extern "C" void kernel_launch(void* const* d_in, const int* in_sizes, int n_in,
                              void* d_out, int out_size)
{
    const float* x  = (const float*)d_in[0];
    const float* Wq = (const float*)d_in[1];
    const float* bq = (const float*)d_in[2];
    const float* Wk = (const float*)d_in[3];
    const float* bk = (const float*)d_in[4];
    const float* Wv = (const float*)d_in[5];
    const float* bv = (const float*)d_in[6];
    const float* Wo = (const float*)d_in[7];
    const float* bo = (const float*)d_in[8];
    float* out = (float*)d_out;

    dim3 blk(256);
    proj_kernel<<<dim3(DM / 128, (Bb * L) / 128, 3), blk>>>(x, Wq, bq, Wk, bk, Wv, bv);
    scores_kernel<<<dim3(L / 128, L / 128, BH), blk>>>();
    topk_av_kernel<<<(BH * L) / 8, blk>>>();
    outproj_kernel<<<dim3(DM / 128, (Bb * L) / 128), blk>>>(Wo, bo, out);
}

// round 11
// speedup vs baseline: 1.8375x; 1.1231x over previous
#include <cuda_runtime.h>
#include <cuda_bf16.h>
#include <cstdint>

#define FULLMASK 0xFFFFFFFFu

static constexpr int Bb = 2;
static constexpr int L  = 2048;
static constexpr int DM = 512;
static constexpr int H  = 8;
static constexpr int DK = 64;
static constexpr int U  = 38;     // int(5 * ln(2048)) = 38
static constexpr int BH = Bb * H; // 16

// ---------------- scratch (static device globals; no allocation) ----------------
__device__ float g_Q[(size_t)BH * L * DK];     // 8 MB  head-major [bh][l][d]
__device__ float g_K[(size_t)BH * L * DK];     // 8 MB
__device__ float g_V[(size_t)BH * L * DK];     // 8 MB
__device__ float g_S[(size_t)BH * L * L];      // 256 MB approx scores [bh][q][k]
__device__ float g_AO[(size_t)Bb * L * DM];    // 8 MB
__device__ __nv_bfloat16 g_Qh[(size_t)BH * L * DK];   // bf16 splits (4 MB each)
__device__ __nv_bfloat16 g_Ql[(size_t)BH * L * DK];
__device__ __nv_bfloat16 g_Kh[(size_t)BH * L * DK];
__device__ __nv_bfloat16 g_Kl[(size_t)BH * L * DK];

// ---------------- packed fp32x2 helpers (sm_103a FFMA2) ----------------
__device__ __forceinline__ unsigned long long pk2(float lo, float hi)
{
    unsigned long long r;
    asm("mov.b64 %0, {%1, %2};" : "=l"(r) : "f"(lo), "f"(hi));
    return r;
}
__device__ __forceinline__ void upk2(unsigned long long p, float& lo, float& hi)
{
    asm("mov.b64 {%0, %1}, %2;" : "=f"(lo), "=f"(hi) : "l"(p));
}
__device__ __forceinline__ void ffma2(unsigned long long& d,
                                      unsigned long long a, unsigned long long b)
{
    asm("fma.rn.f32x2 %0, %1, %2, %0;" : "+l"(d) : "l"(a), "l"(b));
}

// =====================================================================
// FFMA2 SGEMM core: C(128x128) += A(128xK)*B(128xK)^T  (both K-major)
// =====================================================================
__device__ __forceinline__ void gemm_core_128(
    const float* __restrict__ A, const float* __restrict__ Bm,
    int lda, int ldb, int Kc, float (&acc)[8][8])
{
    __shared__ float As[16][132];
    __shared__ float Bs[16][132];

    const int tid = threadIdx.x;
    const int tx  = tid & 15;
    const int ty  = tid >> 4;
    const int lr  = tid >> 2;
    const int lc  = (tid & 3) << 2;

    unsigned long long acc2[8][4];
    #pragma unroll
    for (int i = 0; i < 8; ++i)
        #pragma unroll
        for (int j = 0; j < 4; ++j) acc2[i][j] = 0ULL;

    float4 a0, a1, b0, b1;
    a0 = *(const float4*)(A + (size_t)lr * lda + lc);
    a1 = *(const float4*)(A + (size_t)(lr + 64) * lda + lc);
    b0 = *(const float4*)(Bm + (size_t)lr * ldb + lc);
    b1 = *(const float4*)(Bm + (size_t)(lr + 64) * ldb + lc);

    const int nk = Kc >> 4;
    for (int kt = 0; kt < nk; ++kt) {
        As[lc + 0][lr]      = a0.x; As[lc + 1][lr]      = a0.y;
        As[lc + 2][lr]      = a0.z; As[lc + 3][lr]      = a0.w;
        As[lc + 0][lr + 64] = a1.x; As[lc + 1][lr + 64] = a1.y;
        As[lc + 2][lr + 64] = a1.z; As[lc + 3][lr + 64] = a1.w;
        Bs[lc + 0][lr]      = b0.x; Bs[lc + 1][lr]      = b0.y;
        Bs[lc + 2][lr]      = b0.z; Bs[lc + 3][lr]      = b0.w;
        Bs[lc + 0][lr + 64] = b1.x; Bs[lc + 1][lr + 64] = b1.y;
        Bs[lc + 2][lr + 64] = b1.z; Bs[lc + 3][lr + 64] = b1.w;
        __syncthreads();

        if (kt + 1 < nk) {
            const int k0 = (kt + 1) << 4;
            a0 = *(const float4*)(A + (size_t)lr * lda + k0 + lc);
            a1 = *(const float4*)(A + (size_t)(lr + 64) * lda + k0 + lc);
            b0 = *(const float4*)(Bm + (size_t)lr * ldb + k0 + lc);
            b1 = *(const float4*)(Bm + (size_t)(lr + 64) * ldb + k0 + lc);
        }

        #pragma unroll
        for (int c = 0; c < 16; ++c) {
            float4 af0 = *(const float4*)&As[c][ty * 4];
            float4 af1 = *(const float4*)&As[c][64 + ty * 4];
            float4 bf0 = *(const float4*)&Bs[c][tx * 4];
            float4 bf1 = *(const float4*)&Bs[c][64 + tx * 4];

            unsigned long long bp[4], ap[8];
            bp[0] = pk2(bf0.x, bf0.y); bp[1] = pk2(bf0.z, bf0.w);
            bp[2] = pk2(bf1.x, bf1.y); bp[3] = pk2(bf1.z, bf1.w);
            ap[0] = pk2(af0.x, af0.x); ap[1] = pk2(af0.y, af0.y);
            ap[2] = pk2(af0.z, af0.z); ap[3] = pk2(af0.w, af0.w);
            ap[4] = pk2(af1.x, af1.x); ap[5] = pk2(af1.y, af1.y);
            ap[6] = pk2(af1.z, af1.z); ap[7] = pk2(af1.w, af1.w);

            #pragma unroll
            for (int i = 0; i < 8; ++i)
                #pragma unroll
                for (int jj = 0; jj < 4; ++jj)
                    ffma2(acc2[i][jj], ap[i], bp[jj]);
        }
        __syncthreads();
    }

    #pragma unroll
    for (int i = 0; i < 8; ++i)
        #pragma unroll
        for (int jj = 0; jj < 4; ++jj)
            upk2(acc2[i][jj], acc[i][2 * jj], acc[i][2 * jj + 1]);
}

__device__ __forceinline__ int mt_ofs(int t4, int i)
{
    return (i < 4) ? (t4 * 4 + i) : (64 + t4 * 4 + (i - 4));
}

// =====================================================================
// Kernel 1: fused QKV projections + bf16 hi/lo split emission for Q,K.
// =====================================================================
__global__ __launch_bounds__(256)
void proj_kernel(const float* __restrict__ x,
                 const float* __restrict__ Wq, const float* __restrict__ bq,
                 const float* __restrict__ Wk, const float* __restrict__ bk,
                 const float* __restrict__ Wv, const float* __restrict__ bv)
{
    const float* W; const float* bias; float* dst;
    __nv_bfloat16* dh = nullptr; __nv_bfloat16* dl = nullptr;
    if (blockIdx.z == 0)      { W = Wq; bias = bq; dst = g_Q; dh = g_Qh; dl = g_Ql; }
    else if (blockIdx.z == 1) { W = Wk; bias = bk; dst = g_K; dh = g_Kh; dl = g_Kl; }
    else                      { W = Wv; bias = bv; dst = g_V; }

    const float* A  = x + (size_t)blockIdx.y * 128 * DM;
    const float* Bm = W + (size_t)blockIdx.x * 128 * DM;

    float acc[8][8];
    gemm_core_128(A, Bm, DM, DM, DM, acc);

    const int tx = threadIdx.x & 15, ty = threadIdx.x >> 4;
    #pragma unroll
    for (int i = 0; i < 8; ++i) {
        const int gi = blockIdx.y * 128 + mt_ofs(ty, i);
        const int b  = gi >> 11, l = gi & 2047;
        #pragma unroll
        for (int jh = 0; jh < 2; ++jh) {
            const int o = blockIdx.x * 128 + (jh ? 64 + tx * 4 : tx * 4);
            const int h = o >> 6, d = o & 63;
            float4 r = make_float4(acc[i][jh * 4 + 0] + bias[o + 0],
                                   acc[i][jh * 4 + 1] + bias[o + 1],
                                   acc[i][jh * 4 + 2] + bias[o + 2],
                                   acc[i][jh * 4 + 3] + bias[o + 3]);
            const size_t off = (((size_t)(b * H + h) * L) + l) * DK + d;
            *(float4*)&dst[off] = r;
            if (dh) {
                const float vv[4] = {r.x, r.y, r.z, r.w};
                __nv_bfloat16 hv[4], lv[4];
                #pragma unroll
                for (int e = 0; e < 4; ++e) {
                    hv[e] = __float2bfloat16(vv[e]);
                    lv[e] = __float2bfloat16(vv[e] - __bfloat162float(hv[e]));
                }
                *(uint64_t*)&dh[off] = *(const uint64_t*)hv;
                *(uint64_t*)&dl[off] = *(const uint64_t*)lv;
            }
        }
    }
}

// =====================================================================
// Kernel 2: S_approx = (Qh*Kh + Qh*Kl + Ql*Kh)/8 via warp-level bf16
// mma.sync (fallback HMMA; tcgen05 is not accepted by the harness's
// ptxas target).  Equivalent single GEMM with K=192 run as 3 K=64
// segments; A tile (Qh) reused for segments 0-1.
// grid (L/128 k-tiles, L/128 q-tiles, BH), 256 threads = 8 warps (4Mx2N),
// warp tile 32x64 = 2 m-frags x 8 n-frags of m16n8k16.
// =====================================================================
static constexpr int SMMA_STRIDE = 72;   // bf16 elems/row: 144B -> LDSM conflict-free

__device__ __forceinline__ void ldsm_x4(uint32_t& r0, uint32_t& r1,
                                        uint32_t& r2, uint32_t& r3, uint32_t a)
{
    asm volatile("ldmatrix.sync.aligned.m8n8.x4.shared.b16 {%0,%1,%2,%3}, [%4];"
                 : "=r"(r0), "=r"(r1), "=r"(r2), "=r"(r3) : "r"(a));
}
__device__ __forceinline__ void mma_bf16(float* d, const uint32_t* a, const uint32_t* b)
{
    asm volatile(
        "mma.sync.aligned.m16n8k16.row.col.f32.bf16.bf16.f32 "
        "{%0,%1,%2,%3}, {%4,%5,%6,%7}, {%8,%9}, {%0,%1,%2,%3};"
        : "+f"(d[0]), "+f"(d[1]), "+f"(d[2]), "+f"(d[3])
        : "r"(a[0]), "r"(a[1]), "r"(a[2]), "r"(a[3]), "r"(b[0]), "r"(b[1]));
}

__global__ __launch_bounds__(256)
void scores_mma_kernel()
{
    __shared__ __align__(16) __nv_bfloat16 As[128 * SMMA_STRIDE];
    __shared__ __align__(16) __nv_bfloat16 Bs[128 * SMMA_STRIDE];

    const int tid  = threadIdx.x;
    const int wid  = tid >> 5;
    const int lane = tid & 31;
    const int wm   = wid & 3;        // warp M position (32 rows each)
    const int wn   = wid >> 2;       // warp N position (64 cols each)
    const int kt = blockIdx.x, qt = blockIdx.y, bh = blockIdx.z;

    const uint32_t as_b = (uint32_t)__cvta_generic_to_shared(As);
    const uint32_t bs_b = (uint32_t)__cvta_generic_to_shared(Bs);

    float acc[2][8][4];
    #pragma unroll
    for (int mf = 0; mf < 2; ++mf)
        #pragma unroll
        for (int nf = 0; nf < 8; ++nf)
            #pragma unroll
            for (int e = 0; e < 4; ++e) acc[mf][nf][e] = 0.f;

    // copy indices: thread t -> row t>>1, 4 uint4 (32 bf16) at half (t&1)
    const int crow = tid >> 1;
    const int ccol = (tid & 1) * 32;

    const __nv_bfloat16* Aseg[3] = {
        g_Qh + ((size_t)bh * L + qt * 128) * DK,
        g_Qh + ((size_t)bh * L + qt * 128) * DK,
        g_Ql + ((size_t)bh * L + qt * 128) * DK };
    const __nv_bfloat16* Bseg[3] = {
        g_Kh + ((size_t)bh * L + kt * 128) * DK,
        g_Kl + ((size_t)bh * L + kt * 128) * DK,
        g_Kh + ((size_t)bh * L + kt * 128) * DK };

    #pragma unroll
    for (int s = 0; s < 3; ++s) {
        if (s != 1) {   // A changes only for segment 2 (and initial)
            const uint4* src = (const uint4*)(Aseg[s] + (size_t)crow * DK + ccol);
            uint4* dstp = (uint4*)(As + crow * SMMA_STRIDE + ccol);
            #pragma unroll
            for (int i = 0; i < 4; ++i) dstp[i] = src[i];
        }
        {
            const uint4* src = (const uint4*)(Bseg[s] + (size_t)crow * DK + ccol);
            uint4* dstp = (uint4*)(Bs + crow * SMMA_STRIDE + ccol);
            #pragma unroll
            for (int i = 0; i < 4; ++i) dstp[i] = src[i];
        }
        __syncthreads();

        #pragma unroll
        for (int kk = 0; kk < 64; kk += 16) {
            uint32_t af[2][4], bf[8][2];
            #pragma unroll
            for (int mf = 0; mf < 2; ++mf) {
                const int r = wm * 32 + mf * 16 + (lane & 15);
                const int c = kk + (lane >> 4) * 8;
                ldsm_x4(af[mf][0], af[mf][1], af[mf][2], af[mf][3],
                        as_b + (uint32_t)(r * SMMA_STRIDE + c) * 2u);
            }
            #pragma unroll
            for (int p = 0; p < 4; ++p) {
                const int n = wn * 64 + (2 * p + (lane >> 4)) * 8 + (lane & 7);
                const int c = kk + ((lane >> 3) & 1) * 8;
                ldsm_x4(bf[2 * p][0], bf[2 * p][1], bf[2 * p + 1][0], bf[2 * p + 1][1],
                        bs_b + (uint32_t)(n * SMMA_STRIDE + c) * 2u);
            }
            #pragma unroll
            for (int mf = 0; mf < 2; ++mf)
                #pragma unroll
                for (int nf = 0; nf < 8; ++nf)
                    mma_bf16(acc[mf][nf], af[mf], bf[nf]);
        }
        __syncthreads();
    }

    // epilogue: scale by 1/8, streamed stores
    float* Sbh = g_S + (size_t)bh * L * L;
    const int mbase = qt * 128 + wm * 32;
    const int nbase = kt * 128 + wn * 64;
    #pragma unroll
    for (int mf = 0; mf < 2; ++mf)
        #pragma unroll
        for (int nf = 0; nf < 8; ++nf) {
            const int r  = mbase + mf * 16 + (lane >> 2);
            const int cc = nbase + nf * 8 + (lane & 3) * 2;
            float2 v0 = make_float2(acc[mf][nf][0] * 0.125f, acc[mf][nf][1] * 0.125f);
            float2 v1 = make_float2(acc[mf][nf][2] * 0.125f, acc[mf][nf][3] * 0.125f);
            __stcs((float2*)&Sbh[(size_t)r * L + cc], v0);
            __stcs((float2*)&Sbh[(size_t)(r + 8) * L + cc], v1);
        }
}

// =====================================================================
// Kernel 3: approx top-38 + margin -> exact fp32 candidate refinement ->
// exact top-38 threshold + softmax + sparse AV.  Warp per (bh,q) row.
// Approx value index mapping: idx = (t>>2)*128 + lane*4 + (t&3).
// =====================================================================
__device__ __forceinline__ unsigned f2key(float f)
{
    unsigned u = __float_as_uint(f);
    return u ^ (((unsigned)((int)u >> 31)) | 0x80000000u);
}
__device__ __forceinline__ float key2f(unsigned k)
{
    unsigned u = (k & 0x80000000u) ? (k ^ 0x80000000u) : ~k;
    return __uint_as_float(u);
}

__global__ __launch_bounds__(256)
void topk_av_kernel()
{
    __shared__ float          s_w[8][64];
    __shared__ unsigned short s_i[8][64];
    __shared__ float          s_q[8][64];

    const int w    = threadIdx.x >> 5;
    const int lane = threadIdx.x & 31;
    const int row  = blockIdx.x * 8 + w;
    const int bh   = row >> 11;
    const int q    = row & 2047;

    const float* srow = g_S + (size_t)row * L;

    unsigned u[64];
    #pragma unroll
    for (int c = 0; c < 16; ++c) {
        const float4 f = __ldcs((const float4*)(srow + c * 128 + lane * 4));
        u[c * 4 + 0] = f2key(f.x);
        u[c * 4 + 1] = f2key(f.y);
        u[c * 4 + 2] = f2key(f.z);
        u[c * 4 + 3] = f2key(f.w);
    }

    // ---- approximate 38th-largest (bit search on approx keys) ----
    unsigned T = 0;
    bool found = false;
    for (int b = 31; b >= 0 && !found; --b) {
        const unsigned cand = T | (1u << b);
        int cnt = 0;
        #pragma unroll
        for (int t = 0; t < 64; ++t) cnt += (u[t] >= cand);
        cnt = __reduce_add_sync(FULLMASK, cnt);
        if (cnt >= U) T = cand;
        if (cnt == U) found = true;
    }
    {
        unsigned mn = 0xFFFFFFFFu;
        #pragma unroll
        for (int t = 0; t < 64; ++t)
            if (u[t] >= T) mn = min(mn, u[t]);
        T = __reduce_min_sync(FULLMASK, mn);
    }

    // ---- candidates: approx score >= T_approx - margin ----
    const unsigned Tc = f2key(key2f(T) - 0.008f);
    int base = 0;
    #pragma unroll
    for (int t = 0; t < 64; ++t) {
        const bool sel = (u[t] >= Tc);
        const unsigned bal = __ballot_sync(FULLMASK, sel);
        if (sel) {
            const int p = base + __popc(bal & ((1u << lane) - 1u));
            if (p < 64)
                s_i[w][p] = (unsigned short)((t >> 2) * 128 + lane * 4 + (t & 3));
        }
        base += __popc(bal);
    }
    const int nsel = min(base, 64);

    // ---- exact fp32 recompute of candidate scores ----
    {
        const float2 q2 = *(const float2*)(g_Q + ((size_t)bh * L + q) * DK + 2 * lane);
        s_q[w][2 * lane]     = q2.x;
        s_q[w][2 * lane + 1] = q2.y;
    }
    __syncwarp();
    const float* Kbh = g_K + (size_t)bh * L * DK;
    #pragma unroll
    for (int cc = 0; cc < 2; ++cc) {
        const int j = lane + 32 * cc;
        float sc = -1e30f;
        if (j < nsel) {
            const float4* kr = (const float4*)(Kbh + (size_t)s_i[w][j] * DK);
            const float4* qr = (const float4*)s_q[w];
            float a = 0.f;
            #pragma unroll
            for (int i = 0; i < 16; ++i) {
                const float4 kv = kr[i], qv = qr[i];
                a += kv.x * qv.x + kv.y * qv.y + kv.z * qv.z + kv.w * qv.w;
            }
            sc = a * 0.125f;
        }
        s_w[w][j] = sc;
    }
    __syncwarp();

    // ---- exact top-38 among candidates ----
    const float e0 = s_w[w][lane], e1 = s_w[w][lane + 32];
    const unsigned short i0 = s_i[w][lane], i1 = s_i[w][lane + 32];
    const unsigned k0 = f2key(e0), k1 = f2key(e1);
    const unsigned mk = __reduce_max_sync(FULLMASK, max(k0, k1));
    const float m = key2f(mk);

    unsigned Te = 0;
    found = false;
    for (int b = 31; b >= 0 && !found; --b) {
        const unsigned cand = Te | (1u << b);
        const int cnt = __reduce_add_sync(FULLMASK, (int)(k0 >= cand) + (int)(k1 >= cand));
        if (cnt >= U) Te = cand;
        if (cnt == U) found = true;
    }
    {
        unsigned mn = 0xFFFFFFFFu;
        if (k0 >= Te) mn = min(mn, k0);
        if (k1 >= Te) mn = min(mn, k1);
        Te = __reduce_min_sync(FULLMASK, mn);
    }

    // ---- exact softmax weights + compact selected ----
    const float w0 = (k0 >= Te) ? __expf(e0 - m) : 0.f;
    const float w1 = (k1 >= Te) ? __expf(e1 - m) : 0.f;
    float Z = w0 + w1;
    #pragma unroll
    for (int off = 16; off; off >>= 1)
        Z += __shfl_xor_sync(FULLMASK, Z, off);
    const float invZ = 1.f / Z;

    const unsigned bal0 = __ballot_sync(FULLMASK, k0 >= Te);
    const unsigned bal1 = __ballot_sync(FULLMASK, k1 >= Te);
    const int n0 = __popc(bal0);
    __syncwarp();
    if (k0 >= Te) {
        const int p = __popc(bal0 & ((1u << lane) - 1u));
        s_w[w][p] = w0; s_i[w][p] = i0;
    }
    if (k1 >= Te) {
        const int p = n0 + __popc(bal1 & ((1u << lane) - 1u));
        s_w[w][p] = w1; s_i[w][p] = i1;
    }
    const int nsel2 = n0 + __popc(bal1);
    __syncwarp();

    // ---- batched sparse AV over selected list ----
    const float* Vh = g_V + (size_t)bh * L * DK;
    float o0 = 0.f, o1 = 0.f;
    int j = 0;
    for (; j + 4 <= nsel2; j += 4) {
        const float a0 = s_w[w][j],     a1 = s_w[w][j + 1];
        const float a2 = s_w[w][j + 2], a3 = s_w[w][j + 3];
        const float* v0 = Vh + (size_t)s_i[w][j]     * DK;
        const float* v1 = Vh + (size_t)s_i[w][j + 1] * DK;
        const float* v2 = Vh + (size_t)s_i[w][j + 2] * DK;
        const float* v3 = Vh + (size_t)s_i[w][j + 3] * DK;
        const float x0 = v0[lane], y0 = v0[lane + 32];
        const float x1 = v1[lane], y1 = v1[lane + 32];
        const float x2 = v2[lane], y2 = v2[lane + 32];
        const float x3 = v3[lane], y3 = v3[lane + 32];
        o0 += a0 * x0 + a1 * x1 + a2 * x2 + a3 * x3;
        o1 += a0 * y0 + a1 * y1 + a2 * y2 + a3 * y3;
    }
    for (; j < nsel2; ++j) {
        const float wj = s_w[w][j];
        const float* vr = Vh + (size_t)s_i[w][j] * DK;
        o0 += wj * vr[lane];
        o1 += wj * vr[lane + 32];
    }

    const int b = bh >> 3, h = bh & 7;
    float* ao = g_AO + (size_t)(b * L + q) * DM + h * DK;
    ao[lane]      = o0 * invZ;
    ao[lane + 32] = o1 * invZ;
}

// =====================================================================
// Kernel 4: out = AO @ Wo^T + bo.
// =====================================================================
__global__ __launch_bounds__(256)
void outproj_kernel(const float* __restrict__ Wo, const float* __restrict__ bo,
                    float* __restrict__ out)
{
    const float* A  = g_AO + (size_t)blockIdx.y * 128 * DM;
    const float* Bm = Wo   + (size_t)blockIdx.x * 128 * DM;

    float acc[8][8];
    gemm_core_128(A, Bm, DM, DM, DM, acc);

    const int tx = threadIdx.x & 15, ty = threadIdx.x >> 4;
    #pragma unroll
    for (int i = 0; i < 8; ++i) {
        const int r = blockIdx.y * 128 + mt_ofs(ty, i);
        #pragma unroll
        for (int jh = 0; jh < 2; ++jh) {
            const int cc = blockIdx.x * 128 + (jh ? 64 + tx * 4 : tx * 4);
            float4 v = make_float4(acc[i][jh * 4 + 0] + bo[cc + 0],
                                   acc[i][jh * 4 + 1] + bo[cc + 1],
                                   acc[i][jh * 4 + 2] + bo[cc + 2],
                                   acc[i][jh * 4 + 3] + bo[cc + 3]);
            *(float4*)&out[(size_t)r * DM + cc] = v;
        }
    }
}

// =====================================================================
extern "C" void kernel_launch(void* const* d_in, const int* in_sizes, int n_in,
                              void* d_out, int out_size)
{
    const float* x  = (const float*)d_in[0];
    const float* Wq = (const float*)d_in[1];
    const float* bq = (const float*)d_in[2];
    const float* Wk = (const float*)d_in[3];
    const float* bk = (const float*)d_in[4];
    const float* Wv = (const float*)d_in[5];
    const float* bv = (const float*)d_in[6];
    const float* Wo = (const float*)d_in[7];
    const float* bo = (const float*)d_in[8];
    float* out = (float*)d_out;

    dim3 blk(256);
    proj_kernel<<<dim3(DM / 128, (Bb * L) / 128, 3), blk>>>(x, Wq, bq, Wk, bk, Wv, bv);
    scores_mma_kernel<<<dim3(L / 128, L / 128, BH), blk>>>();
    topk_av_kernel<<<(BH * L) / 8, blk>>>();
    outproj_kernel<<<dim3(DM / 128, (Bb * L) / 128), blk>>>(Wo, bo, out);
}

// round 15
// speedup vs baseline: 1.9493x; 1.0608x over previous
#include <cuda_runtime.h>
#include <cuda_bf16.h>
#include <cstdint>

#define FULLMASK 0xFFFFFFFFu

static constexpr int Bb = 2;
static constexpr int L  = 2048;
static constexpr int DM = 512;
static constexpr int H  = 8;
static constexpr int DK = 64;
static constexpr int U  = 38;     // int(5 * ln(2048)) = 38
static constexpr int BH = Bb * H; // 16
static constexpr int NC = 96;     // candidate buffer size (3 per lane)

// ---------------- scratch (static device globals; no allocation) ----------------
__device__ float g_Q[(size_t)BH * L * DK];     // 8 MB  head-major [bh][l][d]
__device__ float g_K[(size_t)BH * L * DK];     // 8 MB
__device__ float g_V[(size_t)BH * L * DK];     // 8 MB
__device__ __nv_bfloat16 g_Sb[(size_t)BH * L * L];  // 128 MB approx scores (bf16)
__device__ float g_AO[(size_t)Bb * L * DM];    // 8 MB
__device__ __nv_bfloat16 g_Qb[(size_t)BH * L * DK]; // 4 MB bf16 Q
__device__ __nv_bfloat16 g_Kb[(size_t)BH * L * DK]; // 4 MB bf16 K

// ---------------- packed fp32x2 helpers (sm_103a FFMA2) ----------------
__device__ __forceinline__ unsigned long long pk2(float lo, float hi)
{
    unsigned long long r;
    asm("mov.b64 %0, {%1, %2};" : "=l"(r) : "f"(lo), "f"(hi));
    return r;
}
__device__ __forceinline__ void upk2(unsigned long long p, float& lo, float& hi)
{
    asm("mov.b64 {%0, %1}, %2;" : "=f"(lo), "=f"(hi) : "l"(p));
}
__device__ __forceinline__ void ffma2(unsigned long long& d,
                                      unsigned long long a, unsigned long long b)
{
    asm("fma.rn.f32x2 %0, %1, %2, %0;" : "+l"(d) : "l"(a), "l"(b));
}

// =====================================================================
// FFMA2 SGEMM core: C(128x128) += A(128xK)*B(128xK)^T  (both K-major)
// =====================================================================
__device__ __forceinline__ void gemm_core_128(
    const float* __restrict__ A, const float* __restrict__ Bm,
    int lda, int ldb, int Kc, float (&acc)[8][8])
{
    __shared__ float As[16][132];
    __shared__ float Bs[16][132];

    const int tid = threadIdx.x;
    const int tx  = tid & 15;
    const int ty  = tid >> 4;
    const int lr  = tid >> 2;
    const int lc  = (tid & 3) << 2;

    unsigned long long acc2[8][4];
    #pragma unroll
    for (int i = 0; i < 8; ++i)
        #pragma unroll
        for (int j = 0; j < 4; ++j) acc2[i][j] = 0ULL;

    float4 a0, a1, b0, b1;
    a0 = *(const float4*)(A + (size_t)lr * lda + lc);
    a1 = *(const float4*)(A + (size_t)(lr + 64) * lda + lc);
    b0 = *(const float4*)(Bm + (size_t)lr * ldb + lc);
    b1 = *(const float4*)(Bm + (size_t)(lr + 64) * ldb + lc);

    const int nk = Kc >> 4;
    for (int kt = 0; kt < nk; ++kt) {
        As[lc + 0][lr]      = a0.x; As[lc + 1][lr]      = a0.y;
        As[lc + 2][lr]      = a0.z; As[lc + 3][lr]      = a0.w;
        As[lc + 0][lr + 64] = a1.x; As[lc + 1][lr + 64] = a1.y;
        As[lc + 2][lr + 64] = a1.z; As[lc + 3][lr + 64] = a1.w;
        Bs[lc + 0][lr]      = b0.x; Bs[lc + 1][lr]      = b0.y;
        Bs[lc + 2][lr]      = b0.z; Bs[lc + 3][lr]      = b0.w;
        Bs[lc + 0][lr + 64] = b1.x; Bs[lc + 1][lr + 64] = b1.y;
        Bs[lc + 2][lr + 64] = b1.z; Bs[lc + 3][lr + 64] = b1.w;
        __syncthreads();

        if (kt + 1 < nk) {
            const int k0 = (kt + 1) << 4;
            a0 = *(const float4*)(A + (size_t)lr * lda + k0 + lc);
            a1 = *(const float4*)(A + (size_t)(lr + 64) * lda + k0 + lc);
            b0 = *(const float4*)(Bm + (size_t)lr * ldb + k0 + lc);
            b1 = *(const float4*)(Bm + (size_t)(lr + 64) * ldb + k0 + lc);
        }

        #pragma unroll
        for (int c = 0; c < 16; ++c) {
            float4 af0 = *(const float4*)&As[c][ty * 4];
            float4 af1 = *(const float4*)&As[c][64 + ty * 4];
            float4 bf0 = *(const float4*)&Bs[c][tx * 4];
            float4 bf1 = *(const float4*)&Bs[c][64 + tx * 4];

            unsigned long long bp[4], ap[8];
            bp[0] = pk2(bf0.x, bf0.y); bp[1] = pk2(bf0.z, bf0.w);
            bp[2] = pk2(bf1.x, bf1.y); bp[3] = pk2(bf1.z, bf1.w);
            ap[0] = pk2(af0.x, af0.x); ap[1] = pk2(af0.y, af0.y);
            ap[2] = pk2(af0.z, af0.z); ap[3] = pk2(af0.w, af0.w);
            ap[4] = pk2(af1.x, af1.x); ap[5] = pk2(af1.y, af1.y);
            ap[6] = pk2(af1.z, af1.z); ap[7] = pk2(af1.w, af1.w);

            #pragma unroll
            for (int i = 0; i < 8; ++i)
                #pragma unroll
                for (int jj = 0; jj < 4; ++jj)
                    ffma2(acc2[i][jj], ap[i], bp[jj]);
        }
        __syncthreads();
    }

    #pragma unroll
    for (int i = 0; i < 8; ++i)
        #pragma unroll
        for (int jj = 0; jj < 4; ++jj)
            upk2(acc2[i][jj], acc[i][2 * jj], acc[i][2 * jj + 1]);
}

__device__ __forceinline__ int mt_ofs(int t4, int i)
{
    return (i < 4) ? (t4 * 4 + i) : (64 + t4 * 4 + (i - 4));
}

// =====================================================================
// Kernel 1: fused QKV projections (+ bf16 copy of Q,K for the MMA filter)
// =====================================================================
__global__ __launch_bounds__(256)
void proj_kernel(const float* __restrict__ x,
                 const float* __restrict__ Wq, const float* __restrict__ bq,
                 const float* __restrict__ Wk, const float* __restrict__ bk,
                 const float* __restrict__ Wv, const float* __restrict__ bv)
{
    const float* W; const float* bias; float* dst;
    __nv_bfloat16* db = nullptr;
    if (blockIdx.z == 0)      { W = Wq; bias = bq; dst = g_Q; db = g_Qb; }
    else if (blockIdx.z == 1) { W = Wk; bias = bk; dst = g_K; db = g_Kb; }
    else                      { W = Wv; bias = bv; dst = g_V; }

    const float* A  = x + (size_t)blockIdx.y * 128 * DM;
    const float* Bm = W + (size_t)blockIdx.x * 128 * DM;

    float acc[8][8];
    gemm_core_128(A, Bm, DM, DM, DM, acc);

    const int tx = threadIdx.x & 15, ty = threadIdx.x >> 4;
    #pragma unroll
    for (int i = 0; i < 8; ++i) {
        const int gi = blockIdx.y * 128 + mt_ofs(ty, i);
        const int b  = gi >> 11, l = gi & 2047;
        #pragma unroll
        for (int jh = 0; jh < 2; ++jh) {
            const int o = blockIdx.x * 128 + (jh ? 64 + tx * 4 : tx * 4);
            const int h = o >> 6, d = o & 63;
            float4 r = make_float4(acc[i][jh * 4 + 0] + bias[o + 0],
                                   acc[i][jh * 4 + 1] + bias[o + 1],
                                   acc[i][jh * 4 + 2] + bias[o + 2],
                                   acc[i][jh * 4 + 3] + bias[o + 3]);
            const size_t off = (((size_t)(b * H + h) * L) + l) * DK + d;
            *(float4*)&dst[off] = r;
            if (db) {
                __nv_bfloat16 hv[4] = {
                    __float2bfloat16(r.x), __float2bfloat16(r.y),
                    __float2bfloat16(r.z), __float2bfloat16(r.w)};
                *(uint64_t*)&db[off] = *(const uint64_t*)hv;
            }
        }
    }
}

// =====================================================================
// Kernel 2: S_approx = Qb Kb^T / 8 via warp-level bf16 mma.sync,
// stored bf16.  grid (L/128 k-tiles, L/128 q-tiles, BH), 256 threads =
// 8 warps (4Mx2N), warp tile 32x64 = 2 m-frags x 8 n-frags m16n8k16.
// =====================================================================
static constexpr int SMMA_STRIDE = 72;   // 144B rows -> LDSM conflict-free

__device__ __forceinline__ void ldsm_x4(uint32_t& r0, uint32_t& r1,
                                        uint32_t& r2, uint32_t& r3, uint32_t a)
{
    asm volatile("ldmatrix.sync.aligned.m8n8.x4.shared.b16 {%0,%1,%2,%3}, [%4];"
                 : "=r"(r0), "=r"(r1), "=r"(r2), "=r"(r3) : "r"(a));
}
__device__ __forceinline__ void mma_bf16(float* d, const uint32_t* a, const uint32_t* b)
{
    asm volatile(
        "mma.sync.aligned.m16n8k16.row.col.f32.bf16.bf16.f32 "
        "{%0,%1,%2,%3}, {%4,%5,%6,%7}, {%8,%9}, {%0,%1,%2,%3};"
        : "+f"(d[0]), "+f"(d[1]), "+f"(d[2]), "+f"(d[3])
        : "r"(a[0]), "r"(a[1]), "r"(a[2]), "r"(a[3]), "r"(b[0]), "r"(b[1]));
}

__global__ __launch_bounds__(256)
void scores_mma_kernel()
{
    __shared__ __align__(16) __nv_bfloat16 As[128 * SMMA_STRIDE];
    __shared__ __align__(16) __nv_bfloat16 Bs[128 * SMMA_STRIDE];

    const int tid  = threadIdx.x;
    const int wid  = tid >> 5;
    const int lane = tid & 31;
    const int wm   = wid & 3;        // warp M position (32 rows)
    const int wn   = wid >> 2;       // warp N position (64 cols)
    const int kt = blockIdx.x, qt = blockIdx.y, bh = blockIdx.z;

    const uint32_t as_b = (uint32_t)__cvta_generic_to_shared(As);
    const uint32_t bs_b = (uint32_t)__cvta_generic_to_shared(Bs);

    float acc[2][8][4];
    #pragma unroll
    for (int mf = 0; mf < 2; ++mf)
        #pragma unroll
        for (int nf = 0; nf < 8; ++nf)
            #pragma unroll
            for (int e = 0; e < 4; ++e) acc[mf][nf][e] = 0.f;

    // tile copy: thread t -> row t>>1, 4 uint4 (32 bf16) at half (t&1)
    const int crow = tid >> 1;
    const int ccol = (tid & 1) * 32;
    {
        const uint4* srcA = (const uint4*)(g_Qb + ((size_t)bh * L + qt * 128 + crow) * DK + ccol);
        const uint4* srcB = (const uint4*)(g_Kb + ((size_t)bh * L + kt * 128 + crow) * DK + ccol);
        uint4* dA = (uint4*)(As + crow * SMMA_STRIDE + ccol);
        uint4* dB = (uint4*)(Bs + crow * SMMA_STRIDE + ccol);
        #pragma unroll
        for (int i = 0; i < 4; ++i) { dA[i] = srcA[i]; dB[i] = srcB[i]; }
    }
    __syncthreads();

    #pragma unroll
    for (int kk = 0; kk < 64; kk += 16) {
        uint32_t af[2][4], bf[8][2];
        #pragma unroll
        for (int mf = 0; mf < 2; ++mf) {
            const int r = wm * 32 + mf * 16 + (lane & 15);
            const int c = kk + (lane >> 4) * 8;
            ldsm_x4(af[mf][0], af[mf][1], af[mf][2], af[mf][3],
                    as_b + (uint32_t)(r * SMMA_STRIDE + c) * 2u);
        }
        #pragma unroll
        for (int p = 0; p < 4; ++p) {
            const int n = wn * 64 + (2 * p + (lane >> 4)) * 8 + (lane & 7);
            const int c = kk + ((lane >> 3) & 1) * 8;
            ldsm_x4(bf[2 * p][0], bf[2 * p][1], bf[2 * p + 1][0], bf[2 * p + 1][1],
                    bs_b + (uint32_t)(n * SMMA_STRIDE + c) * 2u);
        }
        #pragma unroll
        for (int mf = 0; mf < 2; ++mf)
            #pragma unroll
            for (int nf = 0; nf < 8; ++nf)
                mma_bf16(acc[mf][nf], af[mf], bf[nf]);
    }

    // epilogue: scale 1/8, convert to bf16x2, streamed 4B stores
    __nv_bfloat16* Sbh = g_Sb + (size_t)bh * L * L;
    const int mbase = qt * 128 + wm * 32;
    const int nbase = kt * 128 + wn * 64;
    #pragma unroll
    for (int mf = 0; mf < 2; ++mf)
        #pragma unroll
        for (int nf = 0; nf < 8; ++nf) {
            const int r  = mbase + mf * 16 + (lane >> 2);
            const int cc = nbase + nf * 8 + (lane & 3) * 2;
            __nv_bfloat162 p0 = __float22bfloat162_rn(
                make_float2(acc[mf][nf][0] * 0.125f, acc[mf][nf][1] * 0.125f));
            __nv_bfloat162 p1 = __float22bfloat162_rn(
                make_float2(acc[mf][nf][2] * 0.125f, acc[mf][nf][3] * 0.125f));
            __stcs((unsigned*)&Sbh[(size_t)r * L + cc], *(unsigned*)&p0);
            __stcs((unsigned*)&Sbh[(size_t)(r + 8) * L + cc], *(unsigned*)&p1);
        }
}

// =====================================================================
// Kernel 3: approx top-38 (bf16 scores) + margin 0.08 -> exact fp32
// candidate refinement (<=96 candidates) -> exact top-38 + softmax +
// sparse AV.  Warp per (bh,q) row.
// Approx value index mapping: idx = (t>>3)*256 + lane*8 + (t&7).
// =====================================================================
__device__ __forceinline__ unsigned f2key(float f)
{
    unsigned u = __float_as_uint(f);
    return u ^ (((unsigned)((int)u >> 31)) | 0x80000000u);
}
__device__ __forceinline__ float key2f(unsigned k)
{
    unsigned u = (k & 0x80000000u) ? (k ^ 0x80000000u) : ~k;
    return __uint_as_float(u);
}
__device__ __forceinline__ unsigned bkey_lo(unsigned v)  // low bf16 of u32
{
    return f2key(__uint_as_float(v << 16));
}
__device__ __forceinline__ unsigned bkey_hi(unsigned v)  // high bf16 of u32
{
    return f2key(__uint_as_float(v & 0xFFFF0000u));
}

__global__ __launch_bounds__(256)
void topk_av_kernel()
{
    __shared__ float          s_w[8][NC];
    __shared__ unsigned short s_i[8][NC];
    __shared__ float          s_q[8][64];

    const int w    = threadIdx.x >> 5;
    const int lane = threadIdx.x & 31;
    const int row  = blockIdx.x * 8 + w;
    const int bh   = row >> 11;
    const int q    = row & 2047;

    const __nv_bfloat16* srow = g_Sb + (size_t)row * L;

    unsigned u[64];
    #pragma unroll
    for (int c = 0; c < 8; ++c) {   // 8 chunks x (uint4 = 8 bf16)
        const uint4 f = __ldcs((const uint4*)(srow + c * 256 + lane * 8));
        u[c * 8 + 0] = bkey_lo(f.x); u[c * 8 + 1] = bkey_hi(f.x);
        u[c * 8 + 2] = bkey_lo(f.y); u[c * 8 + 3] = bkey_hi(f.y);
        u[c * 8 + 4] = bkey_lo(f.z); u[c * 8 + 5] = bkey_hi(f.z);
        u[c * 8 + 6] = bkey_lo(f.w); u[c * 8 + 7] = bkey_hi(f.w);
    }

    // ---- approximate 38th-largest (bit search on approx keys) ----
    unsigned T = 0;
    bool found = false;
    for (int b = 31; b >= 0 && !found; --b) {
        const unsigned cand = T | (1u << b);
        int cnt = 0;
        #pragma unroll
        for (int t = 0; t < 64; ++t) cnt += (u[t] >= cand);
        cnt = __reduce_add_sync(FULLMASK, cnt);
        if (cnt >= U) T = cand;
        if (cnt == U) found = true;
    }
    {
        unsigned mn = 0xFFFFFFFFu;
        #pragma unroll
        for (int t = 0; t < 64; ++t)
            if (u[t] >= T) mn = min(mn, u[t]);
        T = __reduce_min_sync(FULLMASK, mn);
    }

    // ---- candidates: approx >= T_approx - margin (covers approx error) ----
    const unsigned Tc = f2key(key2f(T) - 0.08f);
    int base = 0;
    #pragma unroll
    for (int t = 0; t < 64; ++t) {
        const bool sel = (u[t] >= Tc);
        const unsigned bal = __ballot_sync(FULLMASK, sel);
        if (sel) {
            const int p = base + __popc(bal & ((1u << lane) - 1u));
            if (p < NC)
                s_i[w][p] = (unsigned short)((t >> 3) * 256 + lane * 8 + (t & 7));
        }
        base += __popc(bal);
    }
    const int nsel = min(base, NC);

    // ---- exact fp32 recompute of candidate scores ----
    {
        const float2 q2 = *(const float2*)(g_Q + ((size_t)bh * L + q) * DK + 2 * lane);
        s_q[w][2 * lane]     = q2.x;
        s_q[w][2 * lane + 1] = q2.y;
    }
    __syncwarp();
    const float* Kbh = g_K + (size_t)bh * L * DK;
    #pragma unroll
    for (int cc = 0; cc < 3; ++cc) {
        const int j = lane + 32 * cc;
        float sc = -1e30f;
        if (j < nsel) {
            const float4* kr = (const float4*)(Kbh + (size_t)s_i[w][j] * DK);
            const float4* qr = (const float4*)s_q[w];
            float a = 0.f;
            #pragma unroll
            for (int i = 0; i < 16; ++i) {
                const float4 kv = kr[i], qv = qr[i];
                a += kv.x * qv.x + kv.y * qv.y + kv.z * qv.z + kv.w * qv.w;
            }
            sc = a * 0.125f;
        }
        s_w[w][j] = sc;
    }
    __syncwarp();

    // ---- exact top-38 among candidates ----
    float ev[3]; unsigned short iv[3]; unsigned kv3[3];
    #pragma unroll
    for (int cc = 0; cc < 3; ++cc) {
        ev[cc] = s_w[w][lane + 32 * cc];
        iv[cc] = s_i[w][lane + 32 * cc];
        kv3[cc] = f2key(ev[cc]);
    }
    const unsigned mk = __reduce_max_sync(FULLMASK, max(kv3[0], max(kv3[1], kv3[2])));
    const float m = key2f(mk);

    unsigned Te = 0;
    found = false;
    for (int b = 31; b >= 0 && !found; --b) {
        const unsigned cand = Te | (1u << b);
        const int cnt = __reduce_add_sync(FULLMASK,
            (int)(kv3[0] >= cand) + (int)(kv3[1] >= cand) + (int)(kv3[2] >= cand));
        if (cnt >= U) Te = cand;
        if (cnt == U) found = true;
    }
    {
        unsigned mn = 0xFFFFFFFFu;
        #pragma unroll
        for (int cc = 0; cc < 3; ++cc)
            if (kv3[cc] >= Te) mn = min(mn, kv3[cc]);
        Te = __reduce_min_sync(FULLMASK, mn);
    }

    // ---- exact softmax weights + compact selected ----
    float wv[3]; float Z = 0.f;
    #pragma unroll
    for (int cc = 0; cc < 3; ++cc) {
        wv[cc] = (kv3[cc] >= Te) ? __expf(ev[cc] - m) : 0.f;
        Z += wv[cc];
    }
    #pragma unroll
    for (int off = 16; off; off >>= 1)
        Z += __shfl_xor_sync(FULLMASK, Z, off);
    const float invZ = 1.f / Z;

    int nsel2 = 0;
    __syncwarp();
    #pragma unroll
    for (int cc = 0; cc < 3; ++cc) {
        const bool sel = (kv3[cc] >= Te);
        const unsigned bal = __ballot_sync(FULLMASK, sel);
        if (sel) {
            const int p = nsel2 + __popc(bal & ((1u << lane) - 1u));
            s_w[w][p] = wv[cc]; s_i[w][p] = iv[cc];
        }
        nsel2 += __popc(bal);
    }
    __syncwarp();

    // ---- batched sparse AV over selected list ----
    const float* Vh = g_V + (size_t)bh * L * DK;
    float o0 = 0.f, o1 = 0.f;
    int j = 0;
    for (; j + 4 <= nsel2; j += 4) {
        const float a0 = s_w[w][j],     a1 = s_w[w][j + 1];
        const float a2 = s_w[w][j + 2], a3 = s_w[w][j + 3];
        const float* v0 = Vh + (size_t)s_i[w][j]     * DK;
        const float* v1 = Vh + (size_t)s_i[w][j + 1] * DK;
        const float* v2 = Vh + (size_t)s_i[w][j + 2] * DK;
        const float* v3 = Vh + (size_t)s_i[w][j + 3] * DK;
        const float x0 = v0[lane], y0 = v0[lane + 32];
        const float x1 = v1[lane], y1 = v1[lane + 32];
        const float x2 = v2[lane], y2 = v2[lane + 32];
        const float x3 = v3[lane], y3 = v3[lane + 32];
        o0 += a0 * x0 + a1 * x1 + a2 * x2 + a3 * x3;
        o1 += a0 * y0 + a1 * y1 + a2 * y2 + a3 * y3;
    }
    for (; j < nsel2; ++j) {
        const float wj = s_w[w][j];
        const float* vr = Vh + (size_t)s_i[w][j] * DK;
        o0 += wj * vr[lane];
        o1 += wj * vr[lane + 32];
    }

    const int b = bh >> 3, h = bh & 7;
    float* ao = g_AO + (size_t)(b * L + q) * DM + h * DK;
    ao[lane]      = o0 * invZ;
    ao[lane + 32] = o1 * invZ;
}

// =====================================================================
// Kernel 4: out = AO @ Wo^T + bo.
// =====================================================================
__global__ __launch_bounds__(256)
void outproj_kernel(const float* __restrict__ Wo, const float* __restrict__ bo,
                    float* __restrict__ out)
{
    const float* A  = g_AO + (size_t)blockIdx.y * 128 * DM;
    const float* Bm = Wo   + (size_t)blockIdx.x * 128 * DM;

    float acc[8][8];
    gemm_core_128(A, Bm, DM, DM, DM, acc);

    const int tx = threadIdx.x & 15, ty = threadIdx.x >> 4;
    #pragma unroll
    for (int i = 0; i < 8; ++i) {
        const int r = blockIdx.y * 128 + mt_ofs(ty, i);
        #pragma unroll
        for (int jh = 0; jh < 2; ++jh) {
            const int cc = blockIdx.x * 128 + (jh ? 64 + tx * 4 : tx * 4);
            float4 v = make_float4(acc[i][jh * 4 + 0] + bo[cc + 0],
                                   acc[i][jh * 4 + 1] + bo[cc + 1],
                                   acc[i][jh * 4 + 2] + bo[cc + 2],
                                   acc[i][jh * 4 + 3] + bo[cc + 3]);
            *(float4*)&out[(size_t)r * DM + cc] = v;
        }
    }
}

// =====================================================================
extern "C" void kernel_launch(void* const* d_in, const int* in_sizes, int n_in,
                              void* d_out, int out_size)
{
    const float* x  = (const float*)d_in[0];
    const float* Wq = (const float*)d_in[1];
    const float* bq = (const float*)d_in[2];
    const float* Wk = (const float*)d_in[3];
    const float* bk = (const float*)d_in[4];
    const float* Wv = (const float*)d_in[5];
    const float* bv = (const float*)d_in[6];
    const float* Wo = (const float*)d_in[7];
    const float* bo = (const float*)d_in[8];
    float* out = (float*)d_out;

    dim3 blk(256);
    proj_kernel<<<dim3(DM / 128, (Bb * L) / 128, 3), blk>>>(x, Wq, bq, Wk, bk, Wv, bv);
    scores_mma_kernel<<<dim3(L / 128, L / 128, BH), blk>>>();
    topk_av_kernel<<<(BH * L) / 8, blk>>>();
    outproj_kernel<<<dim3(DM / 128, (Bb * L) / 128), blk>>>(Wo, bo, out);
}